// round 16
// baseline (speedup 1.0000x reference)
#include <cuda_runtime.h>
#include <cuda_bf16.h>
#include <cuda_fp16.h>
#include <cstdint>

#define S_LEN  2048
#define NHEAD  16
#define HDIM   64
#define DMODEL 1024
#define BATCH  4
#define NTOK   (BATCH * S_LEN)   // 8192
#define NBH    (BATCH * NHEAD)   // 64

// Q pre-scale: (1/sqrt(64)) * log2(e) so softmax can use exp2
#define QSCALE 0.1803368801111204f

// ---------------- scratch (no allocations allowed) ----------------
__device__ __half g_qh [NBH * S_LEN * HDIM];      // Q fp16 [bh][s][hd], pre-scaled QSCALE
__device__ __half g_kh [NBH * S_LEN * HDIM];      // K fp16 [bh][s][hd]
__device__ __half g_vh [NBH * S_LEN * HDIM];      // V fp16 [bh][s][hd]
__device__ __half g_ah [NTOK * DMODEL];           // activation fp16 (x, later att)
__device__ __half g_wth[4 * DMODEL * DMODEL];     // W^T fp16: [Wq;Wk;Wv;Wo]

// ================= helpers =================
__device__ __forceinline__ uint32_t smem_u32(const void* p) {
    uint32_t a;
    asm("{ .reg .u64 t; cvta.to.shared.u64 t, %1; cvt.u32.u64 %0, t; }" : "=r"(a) : "l"(p));
    return a;
}
#define CP16(dst, src) \
    asm volatile("cp.async.cg.shared.global [%0], [%1], 16;" :: "r"(dst), "l"(src))
#define CP_COMMIT() asm volatile("cp.async.commit_group;" ::: "memory")
#define CP_WAIT1()  asm volatile("cp.async.wait_group 1;" ::: "memory")
#define CP_WAIT0()  asm volatile("cp.async.wait_group 0;" ::: "memory")

#define LDSM_X4(r0, r1, r2, r3, addr) \
    asm volatile("ldmatrix.sync.aligned.m8n8.x4.shared.b16 {%0,%1,%2,%3}, [%4];" \
        : "=r"(r0), "=r"(r1), "=r"(r2), "=r"(r3) : "r"(addr))
#define LDSM_X2(r0, r1, addr) \
    asm volatile("ldmatrix.sync.aligned.m8n8.x2.shared.b16 {%0,%1}, [%2];" \
        : "=r"(r0), "=r"(r1) : "r"(addr))
#define LDSM_X2T(r0, r1, addr) \
    asm volatile("ldmatrix.sync.aligned.m8n8.x2.trans.shared.b16 {%0,%1}, [%2];" \
        : "=r"(r0), "=r"(r1) : "r"(addr))

// fp16 warp MMA, fp32 accum: D(16x8) += A(16x16) * B(16x8)
#define MMA_F16(d, a, b0, b1) \
    asm volatile("mma.sync.aligned.m16n8k16.row.col.f32.f16.f16.f32 " \
        "{%0,%1,%2,%3}, {%4,%5,%6,%7}, {%8,%9}, {%0,%1,%2,%3};" \
        : "+f"((d)[0]), "+f"((d)[1]), "+f"((d)[2]), "+f"((d)[3]) \
        : "r"((a)[0]), "r"((a)[1]), "r"((a)[2]), "r"((a)[3]), "r"(b0), "r"(b1))

__device__ __forceinline__ uint32_t packh(float lo, float hi) {
    uint32_t r;
    asm("cvt.rn.f16x2.f32 %0, %1, %2;" : "=r"(r) : "f"(hi), "f"(lo));
    return r;
}

// ================= conversion kernels =================
__global__ void convert_h_kernel(const float* __restrict__ in,
                                 __half* __restrict__ out, int n4) {
    int i = blockIdx.x * blockDim.x + threadIdx.x;
    if (i >= n4) return;
    float4 v = ((const float4*)in)[i];
    ((uint32_t*)out)[2*i]   = packh(v.x, v.y);
    ((uint32_t*)out)[2*i+1] = packh(v.z, v.w);
}

__global__ void convert_wt4_kernel(const float* __restrict__ W0, const float* __restrict__ W1,
                                   const float* __restrict__ W2, const float* __restrict__ W3,
                                   __half* __restrict__ dst) {
    __shared__ float sm[32][33];
    const float* W = (blockIdx.z == 0) ? W0 : (blockIdx.z == 1) ? W1
                   : (blockIdx.z == 2) ? W2 : W3;
    __half* hT = dst + (size_t)blockIdx.z * DMODEL * DMODEL;
    int n0 = blockIdx.x * 32, k0 = blockIdx.y * 32;
    int tx = threadIdx.x, ty = threadIdx.y;   // 32 x 8
#pragma unroll
    for (int i = 0; i < 4; i++)
        sm[ty + 8*i][tx] = W[(size_t)(k0 + ty + 8*i) * DMODEL + n0 + tx];
    __syncthreads();
#pragma unroll
    for (int i = 0; i < 4; i++)
        hT[(size_t)(n0 + ty + 8*i) * DMODEL + k0 + tx] = __float2half(sm[tx][ty + 8*i]);
}

// ================= fp16 GEMM, 64x32 warp tile, 8 warps, ldmatrix =================
// C = A*B; A fp16 [M,K], B fp16 transposed [N,K].
// CTA tile 128x128, 8 warps (2 along M x 4 along N), K chunk 32, 3-stage ring.
// mode 0: fp32 C row-major. mode 3: fused QKV scatter (Q scaled QSCALE, K, V fp16).
#define SA       80
#define T_A      0
#define T_B      (128 * SA)
#define STAGE_SZ (2 * 128 * SA)        // 20480
#define GEMM_SMEM (3 * STAGE_SZ)       // 61440
#define NKCH     (DMODEL / 32)

__global__ __launch_bounds__(256, 2)
void gemm_mma_kernel(const __half* __restrict__ A, const __half* __restrict__ B,
                     float* __restrict__ C,
                     __half* __restrict__ Qh, __half* __restrict__ Kh,
                     __half* __restrict__ Vh, int mode)
{
    extern __shared__ char smem[];
    const uint32_t sb = smem_u32(smem);
    const int tid  = threadIdx.x;
    const int lane = tid & 31;
    const int wid  = tid >> 5;
    const int wm   = wid & 1;        // 2 warps along M, 64 rows each
    const int wn   = wid >> 1;       // 4 warps along N, 32 cols each
    const int m0   = blockIdx.y * 128;
    const int n0   = blockIdx.x * 128;
    const int g    = lane >> 2;
    const int t    = lane & 3;

    const int lrow = tid >> 2;       // 0..63 (+64 on p=1)
    const int lch  = tid & 3;        // 16B chunk in 64B row

    const uint32_t aoffA = (uint32_t)(lane & 15) * SA + ((uint32_t)(lane >> 4) << 4);
    const uint32_t aoffB = (uint32_t)(lane & 7) * SA + ((uint32_t)((lane >> 3) & 1) << 4);

    float d[4][4][4];
#pragma unroll
    for (int i = 0; i < 4; i++)
#pragma unroll
        for (int j = 0; j < 4; j++)
#pragma unroll
            for (int e = 0; e < 4; e++) d[i][j][e] = 0.f;

    auto ld_stage = [&](int c) {
        const int koe = c * 32;
        const uint32_t bufb = sb + (uint32_t)(c % 3) * STAGE_SZ;
#pragma unroll
        for (int p = 0; p < 2; p++) {
            int row = lrow + 64 * p;
            size_t ga = (size_t)(m0 + row) * DMODEL + koe + lch * 8;
            size_t gb = (size_t)(n0 + row) * DMODEL + koe + lch * 8;
            uint32_t so = bufb + (uint32_t)row * SA + lch * 16;
            CP16(so + T_A, A + ga);
            CP16(so + T_B, B + gb);
        }
        CP_COMMIT();
    };
    ld_stage(0);
    ld_stage(1);

    for (int c = 0; c < NKCH; c++) {
        if (c + 1 < NKCH) { CP_WAIT1(); } else { CP_WAIT0(); }
        __syncthreads();
        if (c + 2 < NKCH) ld_stage(c + 2);   // overlaps with compute below

        const uint32_t base = sb + (uint32_t)(c % 3) * STAGE_SZ;

        // preload this warp's B fragments for the chunk (4 nj x 2 ks)
        uint32_t bf[2][4][2];
#pragma unroll
        for (int ks = 0; ks < 2; ks++)
#pragma unroll
            for (int nj = 0; nj < 4; nj++) {
                uint32_t rb = base + T_B + (uint32_t)(32 * wn + 8 * nj) * SA
                            + (uint32_t)ks * 32 + aoffB;
                LDSM_X2(bf[ks][nj][0], bf[ks][nj][1], rb);
            }

#pragma unroll
        for (int ks = 0; ks < 2; ks++) {
            uint32_t a[4][4];
#pragma unroll
            for (int mi = 0; mi < 4; mi++) {
                uint32_t ra = base + T_A + (uint32_t)(64 * wm + 16 * mi) * SA
                            + (uint32_t)ks * 32 + aoffA;
                LDSM_X4(a[mi][0], a[mi][1], a[mi][2], a[mi][3], ra);
            }
#pragma unroll
            for (int nj = 0; nj < 4; nj++)
#pragma unroll
                for (int mi = 0; mi < 4; mi++)
                    MMA_F16(d[mi][nj], a[mi], bf[ks][nj][0], bf[ks][nj][1]);
        }
    }

    // ---- epilogue ----
#pragma unroll
    for (int mi = 0; mi < 4; mi++) {
        int r0 = m0 + 64 * wm + 16 * mi + g;
#pragma unroll
        for (int nj = 0; nj < 4; nj++) {
            int n = n0 + 32 * wn + 8 * nj + 2 * t;
            float f0 = d[mi][nj][0], f1 = d[mi][nj][1];
            float f2 = d[mi][nj][2], f3 = d[mi][nj][3];
            if (mode == 0) {
                *(float2*)(C + (size_t)r0 * DMODEL + n)       = make_float2(f0, f1);
                *(float2*)(C + (size_t)(r0 + 8) * DMODEL + n) = make_float2(f2, f3);
            } else {
                int proj = n >> 10, nn = n & 1023;
                int h = nn >> 6, dd = nn & 63;
                int b0 = r0 >> 11, s0 = r0 & 2047;
                int b1 = (r0 + 8) >> 11, s1 = (r0 + 8) & 2047;
                size_t o0 = (((size_t)(b0 * NHEAD + h)) * S_LEN + s0) * HDIM + dd;
                size_t o1 = (((size_t)(b1 * NHEAD + h)) * S_LEN + s1) * HDIM + dd;
                if (proj == 0) {           // Q fp16, pre-scaled QSCALE (log2-domain)
                    *(uint32_t*)(Qh + o0) = packh(f0 * QSCALE, f1 * QSCALE);
                    *(uint32_t*)(Qh + o1) = packh(f2 * QSCALE, f3 * QSCALE);
                } else if (proj == 1) {    // K fp16
                    *(uint32_t*)(Kh + o0) = packh(f0, f1);
                    *(uint32_t*)(Kh + o1) = packh(f2, f3);
                } else {                   // V fp16 (same layout as K)
                    *(uint32_t*)(Vh + o0) = packh(f0, f1);
                    *(uint32_t*)(Vh + o1) = packh(f2, f3);
                }
            }
        }
    }
}

// ================= tensor-core causal flash-attention =================
// Scores in log2 domain (Q pre-scaled by log2e/8) -> softmax uses exp2f.
// QK^T: 1 fp16 MMA. P.V: 1 fp16 MMA, V row-major + ldmatrix.trans.
// 3-stage cp.async ring, ONE __syncthreads per k-tile.
#define AT_STRIDE 144
#define AT_K 0
#define AT_V (64 * AT_STRIDE)
#define AT_STAGE (2 * 64 * AT_STRIDE)   // 18432
#define ATT_SMEM (3 * AT_STAGE)         // 55296

__global__ __launch_bounds__(256, 2)
void attn_tc_kernel(const __half* __restrict__ qh_, const __half* __restrict__ kh_,
                    const __half* __restrict__ vh_, __half* __restrict__ outh)
{
    extern __shared__ char smem[];
    const uint32_t sb = smem_u32(smem);
    const int tid = threadIdx.x, lane = tid & 31, wid = tid >> 5;
    const int g = lane >> 2, t = lane & 3;
    const int qt = (int)gridDim.x - 1 - (int)blockIdx.x;   // heavy tiles first
    const int bh = blockIdx.y;
    const int bidx = bh >> 4, hidx = bh & 15;
    const int qbase = qt * 128;
    const int ktlast = 2 * qt + 1;

    const __half* qh = qh_ + (size_t)bh * (S_LEN * HDIM);
    const __half* kh = kh_ + (size_t)bh * (S_LEN * HDIM);
    const __half* vh = vh_ + (size_t)bh * (S_LEN * HDIM);

    const uint32_t aoffK = (uint32_t)(lane & 7) * AT_STRIDE
                         + ((uint32_t)((lane >> 3) & 1) << 4);
    const uint32_t aoffV = (uint32_t)(lane & 15) * AT_STRIDE;   // trans: 16 s-rows

    uint32_t qf[4][4];
    {
        const int r0 = 16 * wid + g;
        const uint32_t* ph = (const uint32_t*)(qh + (size_t)(qbase + r0) * HDIM);
#pragma unroll
        for (int ks = 0; ks < 4; ks++) {
            qf[ks][0] = ph[8*ks + t];        qf[ks][2] = ph[8*ks + t + 4];
            qf[ks][1] = ph[256 + 8*ks + t];  qf[ks][3] = ph[256 + 8*ks + t + 4];
        }
    }

    float o[8][4];
#pragma unroll
    for (int j = 0; j < 8; j++)
#pragma unroll
        for (int e = 0; e < 4; e++) o[j][e] = 0.f;
    float m0 = -1e30f, m1 = -1e30f, l0 = 0.f, l1 = 0.f;

    const int lrow = tid >> 3, lch = tid & 7;
    auto stage_load = [&](int kt) {
        const uint32_t dst = sb + (uint32_t)(kt % 3) * AT_STAGE;
#pragma unroll
        for (int p = 0; p < 2; p++) {
            int r = lrow + 32 * p;
            uint32_t so = dst + (uint32_t)r * AT_STRIDE + lch * 16;
            CP16(so + AT_K, kh + (size_t)(kt * 64 + r) * HDIM + lch * 8);
            CP16(so + AT_V, vh + (size_t)(kt * 64 + r) * HDIM + lch * 8);
        }
        CP_COMMIT();
    };
    stage_load(0);
    stage_load(1);

    for (int kt = 0; kt <= ktlast; kt++) {
        if (kt + 1 <= ktlast) { CP_WAIT1(); } else { CP_WAIT0(); }
        __syncthreads();                        // single barrier per k-tile
        if (kt + 2 <= ktlast) stage_load(kt + 2);

        const bool active = !(kt == ktlast && wid < 4);
        if (active) {
            const uint32_t tb = sb + (uint32_t)(kt % 3) * AT_STAGE;

            float s[8][4];
#pragma unroll
            for (int j = 0; j < 8; j++)
#pragma unroll
                for (int e = 0; e < 4; e++) s[j][e] = 0.f;
#pragma unroll
            for (int nj = 0; nj < 8; nj++) {
                uint32_t ro = tb + AT_K + (uint32_t)(8 * nj) * AT_STRIDE + aoffK;
#pragma unroll
                for (int ks = 0; ks < 4; ks++) {
                    uint32_t b0, b1;
                    LDSM_X2(b0, b1, ro + (uint32_t)ks * 32);
                    MMA_F16(s[nj], qf[ks], b0, b1);
                }
            }

            if (kt >= 2 * qt) {
                const int kb = (kt - 2 * qt) * 64;
                const int r0 = 16 * wid + g, r1 = r0 + 8;
#pragma unroll
                for (int nj = 0; nj < 8; nj++) {
                    int k0 = kb + 8 * nj + 2 * t, k1 = k0 + 1;
                    if (k0 > r0) s[nj][0] = -1e30f;
                    if (k1 > r0) s[nj][1] = -1e30f;
                    if (k0 > r1) s[nj][2] = -1e30f;
                    if (k1 > r1) s[nj][3] = -1e30f;
                }
            }

            float mx0 = -1e30f, mx1 = -1e30f;
#pragma unroll
            for (int nj = 0; nj < 8; nj++) {
                mx0 = fmaxf(mx0, fmaxf(s[nj][0], s[nj][1]));
                mx1 = fmaxf(mx1, fmaxf(s[nj][2], s[nj][3]));
            }
            mx0 = fmaxf(mx0, __shfl_xor_sync(0xffffffffu, mx0, 1));
            mx0 = fmaxf(mx0, __shfl_xor_sync(0xffffffffu, mx0, 2));
            mx1 = fmaxf(mx1, __shfl_xor_sync(0xffffffffu, mx1, 1));
            mx1 = fmaxf(mx1, __shfl_xor_sync(0xffffffffu, mx1, 2));
            float mn0 = fmaxf(m0, mx0), mn1 = fmaxf(m1, mx1);
            float al0 = exp2f(m0 - mn0), al1 = exp2f(m1 - mn1);
            m0 = mn0; m1 = mn1;

            float rs0 = 0.f, rs1 = 0.f;
#pragma unroll
            for (int nj = 0; nj < 8; nj++) {
                s[nj][0] = exp2f(s[nj][0] - mn0);
                s[nj][1] = exp2f(s[nj][1] - mn0);
                s[nj][2] = exp2f(s[nj][2] - mn1);
                s[nj][3] = exp2f(s[nj][3] - mn1);
                rs0 += s[nj][0] + s[nj][1];
                rs1 += s[nj][2] + s[nj][3];
            }
            rs0 += __shfl_xor_sync(0xffffffffu, rs0, 1);
            rs0 += __shfl_xor_sync(0xffffffffu, rs0, 2);
            rs1 += __shfl_xor_sync(0xffffffffu, rs1, 1);
            rs1 += __shfl_xor_sync(0xffffffffu, rs1, 2);
            l0 = l0 * al0 + rs0;
            l1 = l1 * al1 + rs1;
#pragma unroll
            for (int nj = 0; nj < 8; nj++) {
                o[nj][0] *= al0; o[nj][1] *= al0;
                o[nj][2] *= al1; o[nj][3] *= al1;
            }

            uint32_t pf[4][4];
#pragma unroll
            for (int ksn = 0; ksn < 4; ksn++) {
                int ja = 2 * ksn, jb = ja + 1;
                pf[ksn][0] = packh(s[ja][0], s[ja][1]);
                pf[ksn][1] = packh(s[ja][2], s[ja][3]);
                pf[ksn][2] = packh(s[jb][0], s[jb][1]);
                pf[ksn][3] = packh(s[jb][2], s[jb][3]);
            }

#pragma unroll
            for (int nj = 0; nj < 8; nj++) {
                uint32_t co = tb + AT_V + (uint32_t)(nj * 16) + aoffV;
#pragma unroll
                for (int ksn = 0; ksn < 4; ksn++) {
                    uint32_t b0, b1;
                    LDSM_X2T(b0, b1, co + (uint32_t)(16 * ksn) * AT_STRIDE);
                    MMA_F16(o[nj], pf[ksn], b0, b1);
                }
            }
        }
    }

    // ---- epilogue: normalize, emit att fp16 in [b*s][h*hd] ----
    const float inv0 = 1.f / l0, inv1 = 1.f / l1;
    const int r0 = qbase + 16 * wid + g;
    const size_t base0 = ((size_t)bidx * S_LEN + r0) * DMODEL + hidx * 64 + 2 * t;
#pragma unroll
    for (int nj = 0; nj < 8; nj++) {
        float f0 = o[nj][0] * inv0, f1 = o[nj][1] * inv0;
        float f2 = o[nj][2] * inv1, f3 = o[nj][3] * inv1;
        size_t o0 = base0 + 8 * nj;
        size_t o1 = o0 + 8 * DMODEL;
        *(uint32_t*)(outh + o0) = packh(f0, f1);
        *(uint32_t*)(outh + o1) = packh(f2, f3);
    }
}

// ---------------- launch ----------------
extern "C" void kernel_launch(void* const* d_in, const int* in_sizes, int n_in,
                              void* d_out, int out_size)
{
    const float* x  = (const float*)d_in[0];
    const float* Wq = (const float*)d_in[1];
    const float* Wk = (const float*)d_in[2];
    const float* Wv = (const float*)d_in[3];
    const float* Wo = (const float*)d_in[4];
    float* out = (float*)d_out;

    __half *qh, *kh, *vh, *ah, *wth;
    cudaGetSymbolAddress((void**)&qh,  g_qh);
    cudaGetSymbolAddress((void**)&kh,  g_kh);
    cudaGetSymbolAddress((void**)&vh,  g_vh);
    cudaGetSymbolAddress((void**)&ah,  g_ah);
    cudaGetSymbolAddress((void**)&wth, g_wth);

    cudaFuncSetAttribute(gemm_mma_kernel, cudaFuncAttributeMaxDynamicSharedMemorySize, GEMM_SMEM);
    cudaFuncSetAttribute(attn_tc_kernel, cudaFuncAttributeMaxDynamicSharedMemorySize, ATT_SMEM);

    const int n4 = NTOK * DMODEL / 4;
    const size_t WSZ = (size_t)DMODEL * DMODEL;

    // x -> fp16; all 4 weights -> fp16 W^T in one launch
    convert_h_kernel<<<n4 / 256, 256>>>(x, ah, n4);
    convert_wt4_kernel<<<dim3(DMODEL / 32, DMODEL / 32, 4), dim3(32, 8)>>>(Wq, Wk, Wv, Wo, wth);

    // fused QKV projection (one launch, N = 3072) -> Q, K, V fp16 [b,h,s,hd]
    gemm_mma_kernel<<<dim3(3 * DMODEL / 128, NTOK / 128), 256, GEMM_SMEM>>>(
        ah, wth, nullptr, qh, kh, vh, 3);

    // fused causal attention -> att fp16
    attn_tc_kernel<<<dim3(S_LEN / 128, NBH), 256, ATT_SMEM>>>(qh, kh, vh, ah);

    // output projection
    gemm_mma_kernel<<<dim3(DMODEL / 128, NTOK / 128), 256, GEMM_SMEM>>>(
        ah, wth + 3 * WSZ, out, nullptr, nullptr, nullptr, 0);
}

// round 17
// speedup vs baseline: 1.1049x; 1.1049x over previous
#include <cuda_runtime.h>
#include <cuda_bf16.h>
#include <cuda_fp16.h>
#include <cstdint>

#define S_LEN  2048
#define NHEAD  16
#define HDIM   64
#define DMODEL 1024
#define BATCH  4
#define NTOK   (BATCH * S_LEN)   // 8192
#define NBH    (BATCH * NHEAD)   // 64

// Q pre-scale: (1/sqrt(64)) * log2(e) so softmax can use exp2
#define QSCALE 0.1803368801111204f

// ---------------- scratch (no allocations allowed) ----------------
__device__ __half g_qh [NBH * S_LEN * HDIM];      // Q fp16 [bh][s][hd], pre-scaled QSCALE
__device__ __half g_kh [NBH * S_LEN * HDIM];      // K fp16 [bh][s][hd]
__device__ __half g_vh [NBH * S_LEN * HDIM];      // V fp16 [bh][s][hd]
__device__ __half g_ah [NTOK * DMODEL];           // activation fp16 (x, later att)
__device__ __half g_wth[4 * DMODEL * DMODEL];     // W^T fp16: [Wq;Wk;Wv;Wo]

// ================= helpers =================
__device__ __forceinline__ uint32_t smem_u32(const void* p) {
    uint32_t a;
    asm("{ .reg .u64 t; cvta.to.shared.u64 t, %1; cvt.u32.u64 %0, t; }" : "=r"(a) : "l"(p));
    return a;
}
#define CP16(dst, src) \
    asm volatile("cp.async.cg.shared.global [%0], [%1], 16;" :: "r"(dst), "l"(src))
#define CP_COMMIT() asm volatile("cp.async.commit_group;" ::: "memory")
#define CP_WAIT1()  asm volatile("cp.async.wait_group 1;" ::: "memory")
#define CP_WAIT0()  asm volatile("cp.async.wait_group 0;" ::: "memory")

#define LDSM_X4(r0, r1, r2, r3, addr) \
    asm volatile("ldmatrix.sync.aligned.m8n8.x4.shared.b16 {%0,%1,%2,%3}, [%4];" \
        : "=r"(r0), "=r"(r1), "=r"(r2), "=r"(r3) : "r"(addr))
#define LDSM_X2(r0, r1, addr) \
    asm volatile("ldmatrix.sync.aligned.m8n8.x2.shared.b16 {%0,%1}, [%2];" \
        : "=r"(r0), "=r"(r1) : "r"(addr))
#define LDSM_X2T(r0, r1, addr) \
    asm volatile("ldmatrix.sync.aligned.m8n8.x2.trans.shared.b16 {%0,%1}, [%2];" \
        : "=r"(r0), "=r"(r1) : "r"(addr))

// fp16 warp MMA, fp32 accum: D(16x8) += A(16x16) * B(16x8)
#define MMA_F16(d, a, b0, b1) \
    asm volatile("mma.sync.aligned.m16n8k16.row.col.f32.f16.f16.f32 " \
        "{%0,%1,%2,%3}, {%4,%5,%6,%7}, {%8,%9}, {%0,%1,%2,%3};" \
        : "+f"((d)[0]), "+f"((d)[1]), "+f"((d)[2]), "+f"((d)[3]) \
        : "r"((a)[0]), "r"((a)[1]), "r"((a)[2]), "r"((a)[3]), "r"(b0), "r"(b1))

__device__ __forceinline__ uint32_t packh(float lo, float hi) {
    uint32_t r;
    asm("cvt.rn.f16x2.f32 %0, %1, %2;" : "=r"(r) : "f"(hi), "f"(lo));
    return r;
}

// ================= conversion kernels =================
__global__ void convert_h_kernel(const float* __restrict__ in,
                                 __half* __restrict__ out, int n4) {
    int i = blockIdx.x * blockDim.x + threadIdx.x;
    if (i >= n4) return;
    float4 v = ((const float4*)in)[i];
    ((uint32_t*)out)[2*i]   = packh(v.x, v.y);
    ((uint32_t*)out)[2*i+1] = packh(v.z, v.w);
}

__global__ void convert_wt4_kernel(const float* __restrict__ W0, const float* __restrict__ W1,
                                   const float* __restrict__ W2, const float* __restrict__ W3,
                                   __half* __restrict__ dst) {
    __shared__ float sm[32][33];
    const float* W = (blockIdx.z == 0) ? W0 : (blockIdx.z == 1) ? W1
                   : (blockIdx.z == 2) ? W2 : W3;
    __half* hT = dst + (size_t)blockIdx.z * DMODEL * DMODEL;
    int n0 = blockIdx.x * 32, k0 = blockIdx.y * 32;
    int tx = threadIdx.x, ty = threadIdx.y;   // 32 x 8
#pragma unroll
    for (int i = 0; i < 4; i++)
        sm[ty + 8*i][tx] = W[(size_t)(k0 + ty + 8*i) * DMODEL + n0 + tx];
    __syncthreads();
#pragma unroll
    for (int i = 0; i < 4; i++)
        hT[(size_t)(n0 + ty + 8*i) * DMODEL + k0 + tx] = __float2half(sm[tx][ty + 8*i]);
}

// ================= fp16 GEMM, 64x64 warp tile, 4 warps, ldmatrix (R15-proven) =================
// C = A*B; A fp16 [M,K], B fp16 transposed [N,K]. 1 MMA per tile op.
// CTA tile 128x128, 4 warps (2x2), K chunk 32, 3-stage cp.async ring.
// mode 0: fp32 C row-major. mode 3: fused QKV scatter (Q scaled QSCALE, K, V fp16).
#define SA       80
#define T_A      0
#define T_B      (128 * SA)
#define STAGE_SZ (2 * 128 * SA)        // 20480
#define GEMM_SMEM (3 * STAGE_SZ)       // 61440
#define NKCH     (DMODEL / 32)

__global__ __launch_bounds__(128, 2)
void gemm_mma_kernel(const __half* __restrict__ A, const __half* __restrict__ B,
                     float* __restrict__ C,
                     __half* __restrict__ Qh, __half* __restrict__ Kh,
                     __half* __restrict__ Vh, int mode)
{
    extern __shared__ char smem[];
    const uint32_t sb = smem_u32(smem);
    const int tid  = threadIdx.x;
    const int lane = tid & 31;
    const int wid  = tid >> 5;
    const int wm   = wid & 1;        // 2 warps along M, 64 rows each
    const int wn   = wid >> 1;       // 2 warps along N, 64 cols each
    const int m0   = blockIdx.y * 128;
    const int n0   = blockIdx.x * 128;
    const int g    = lane >> 2;
    const int t    = lane & 3;

    const int lrow = tid >> 2;       // 0..31 (+32p)
    const int lch  = tid & 3;        // 16B chunk in 64B row

    const uint32_t aoffA = (uint32_t)(lane & 15) * SA + ((uint32_t)(lane >> 4) << 4);
    const uint32_t aoffB = (uint32_t)(lane & 7) * SA + ((uint32_t)((lane >> 3) & 1) << 4);

    float d[4][8][4];
#pragma unroll
    for (int i = 0; i < 4; i++)
#pragma unroll
        for (int j = 0; j < 8; j++)
#pragma unroll
            for (int e = 0; e < 4; e++) d[i][j][e] = 0.f;

    auto ld_stage = [&](int c) {
        const int koe = c * 32;
        const uint32_t bufb = sb + (uint32_t)(c % 3) * STAGE_SZ;
#pragma unroll
        for (int p = 0; p < 4; p++) {
            int row = lrow + 32 * p;
            size_t ga = (size_t)(m0 + row) * DMODEL + koe + lch * 8;
            size_t gb = (size_t)(n0 + row) * DMODEL + koe + lch * 8;
            uint32_t so = bufb + (uint32_t)row * SA + lch * 16;
            CP16(so + T_A, A + ga);
            CP16(so + T_B, B + gb);
        }
        CP_COMMIT();
    };
    ld_stage(0);
    ld_stage(1);

    for (int c = 0; c < NKCH; c++) {
        if (c + 1 < NKCH) { CP_WAIT1(); } else { CP_WAIT0(); }
        __syncthreads();
        if (c + 2 < NKCH) ld_stage(c + 2);   // overlaps with compute below

        const uint32_t base = sb + (uint32_t)(c % 3) * STAGE_SZ;

        // preload ALL B fragments for this chunk
        uint32_t bf[2][8][2];
#pragma unroll
        for (int ks = 0; ks < 2; ks++)
#pragma unroll
            for (int nj = 0; nj < 8; nj++) {
                uint32_t rb = base + T_B + (uint32_t)(64 * wn + 8 * nj) * SA
                            + (uint32_t)ks * 32 + aoffB;
                LDSM_X2(bf[ks][nj][0], bf[ks][nj][1], rb);
            }

#pragma unroll
        for (int ks = 0; ks < 2; ks++) {
            uint32_t a[4][4];
#pragma unroll
            for (int mi = 0; mi < 4; mi++) {
                uint32_t ra = base + T_A + (uint32_t)(64 * wm + 16 * mi) * SA
                            + (uint32_t)ks * 32 + aoffA;
                LDSM_X4(a[mi][0], a[mi][1], a[mi][2], a[mi][3], ra);
            }
#pragma unroll
            for (int nj = 0; nj < 8; nj++)
#pragma unroll
                for (int mi = 0; mi < 4; mi++)
                    MMA_F16(d[mi][nj], a[mi], bf[ks][nj][0], bf[ks][nj][1]);
        }
    }

    // ---- epilogue ----
#pragma unroll
    for (int mi = 0; mi < 4; mi++) {
        int r0 = m0 + 64 * wm + 16 * mi + g;
#pragma unroll
        for (int nj = 0; nj < 8; nj++) {
            int n = n0 + 64 * wn + 8 * nj + 2 * t;
            float f0 = d[mi][nj][0], f1 = d[mi][nj][1];
            float f2 = d[mi][nj][2], f3 = d[mi][nj][3];
            if (mode == 0) {
                *(float2*)(C + (size_t)r0 * DMODEL + n)       = make_float2(f0, f1);
                *(float2*)(C + (size_t)(r0 + 8) * DMODEL + n) = make_float2(f2, f3);
            } else {
                int proj = n >> 10, nn = n & 1023;
                int h = nn >> 6, dd = nn & 63;
                int b0 = r0 >> 11, s0 = r0 & 2047;
                int b1 = (r0 + 8) >> 11, s1 = (r0 + 8) & 2047;
                size_t o0 = (((size_t)(b0 * NHEAD + h)) * S_LEN + s0) * HDIM + dd;
                size_t o1 = (((size_t)(b1 * NHEAD + h)) * S_LEN + s1) * HDIM + dd;
                if (proj == 0) {           // Q fp16, pre-scaled QSCALE (log2-domain)
                    *(uint32_t*)(Qh + o0) = packh(f0 * QSCALE, f1 * QSCALE);
                    *(uint32_t*)(Qh + o1) = packh(f2 * QSCALE, f3 * QSCALE);
                } else if (proj == 1) {    // K fp16
                    *(uint32_t*)(Kh + o0) = packh(f0, f1);
                    *(uint32_t*)(Kh + o1) = packh(f2, f3);
                } else {                   // V fp16 (same layout as K)
                    *(uint32_t*)(Vh + o0) = packh(f0, f1);
                    *(uint32_t*)(Vh + o1) = packh(f2, f3);
                }
            }
        }
    }
}

// ================= tensor-core causal flash-attention (R16-proven) =================
// Scores in log2 domain (Q pre-scaled by log2e/8) -> softmax uses exp2f.
// QK^T: 1 fp16 MMA. P.V: 1 fp16 MMA, V row-major + ldmatrix.trans.
// 3-stage cp.async ring, ONE __syncthreads per k-tile.
#define AT_STRIDE 144
#define AT_K 0
#define AT_V (64 * AT_STRIDE)
#define AT_STAGE (2 * 64 * AT_STRIDE)   // 18432
#define ATT_SMEM (3 * AT_STAGE)         // 55296

__global__ __launch_bounds__(256, 2)
void attn_tc_kernel(const __half* __restrict__ qh_, const __half* __restrict__ kh_,
                    const __half* __restrict__ vh_, __half* __restrict__ outh)
{
    extern __shared__ char smem[];
    const uint32_t sb = smem_u32(smem);
    const int tid = threadIdx.x, lane = tid & 31, wid = tid >> 5;
    const int g = lane >> 2, t = lane & 3;
    const int qt = (int)gridDim.x - 1 - (int)blockIdx.x;   // heavy tiles first
    const int bh = blockIdx.y;
    const int bidx = bh >> 4, hidx = bh & 15;
    const int qbase = qt * 128;
    const int ktlast = 2 * qt + 1;

    const __half* qh = qh_ + (size_t)bh * (S_LEN * HDIM);
    const __half* kh = kh_ + (size_t)bh * (S_LEN * HDIM);
    const __half* vh = vh_ + (size_t)bh * (S_LEN * HDIM);

    const uint32_t aoffK = (uint32_t)(lane & 7) * AT_STRIDE
                         + ((uint32_t)((lane >> 3) & 1) << 4);
    const uint32_t aoffV = (uint32_t)(lane & 15) * AT_STRIDE;   // trans: 16 s-rows

    uint32_t qf[4][4];
    {
        const int r0 = 16 * wid + g;
        const uint32_t* ph = (const uint32_t*)(qh + (size_t)(qbase + r0) * HDIM);
#pragma unroll
        for (int ks = 0; ks < 4; ks++) {
            qf[ks][0] = ph[8*ks + t];        qf[ks][2] = ph[8*ks + t + 4];
            qf[ks][1] = ph[256 + 8*ks + t];  qf[ks][3] = ph[256 + 8*ks + t + 4];
        }
    }

    float o[8][4];
#pragma unroll
    for (int j = 0; j < 8; j++)
#pragma unroll
        for (int e = 0; e < 4; e++) o[j][e] = 0.f;
    float m0 = -1e30f, m1 = -1e30f, l0 = 0.f, l1 = 0.f;

    const int lrow = tid >> 3, lch = tid & 7;
    auto stage_load = [&](int kt) {
        const uint32_t dst = sb + (uint32_t)(kt % 3) * AT_STAGE;
#pragma unroll
        for (int p = 0; p < 2; p++) {
            int r = lrow + 32 * p;
            uint32_t so = dst + (uint32_t)r * AT_STRIDE + lch * 16;
            CP16(so + AT_K, kh + (size_t)(kt * 64 + r) * HDIM + lch * 8);
            CP16(so + AT_V, vh + (size_t)(kt * 64 + r) * HDIM + lch * 8);
        }
        CP_COMMIT();
    };
    stage_load(0);
    stage_load(1);

    for (int kt = 0; kt <= ktlast; kt++) {
        if (kt + 1 <= ktlast) { CP_WAIT1(); } else { CP_WAIT0(); }
        __syncthreads();                        // single barrier per k-tile
        if (kt + 2 <= ktlast) stage_load(kt + 2);

        const bool active = !(kt == ktlast && wid < 4);
        if (active) {
            const uint32_t tb = sb + (uint32_t)(kt % 3) * AT_STAGE;

            float s[8][4];
#pragma unroll
            for (int j = 0; j < 8; j++)
#pragma unroll
                for (int e = 0; e < 4; e++) s[j][e] = 0.f;
#pragma unroll
            for (int nj = 0; nj < 8; nj++) {
                uint32_t ro = tb + AT_K + (uint32_t)(8 * nj) * AT_STRIDE + aoffK;
#pragma unroll
                for (int ks = 0; ks < 4; ks++) {
                    uint32_t b0, b1;
                    LDSM_X2(b0, b1, ro + (uint32_t)ks * 32);
                    MMA_F16(s[nj], qf[ks], b0, b1);
                }
            }

            if (kt >= 2 * qt) {
                const int kb = (kt - 2 * qt) * 64;
                const int r0 = 16 * wid + g, r1 = r0 + 8;
#pragma unroll
                for (int nj = 0; nj < 8; nj++) {
                    int k0 = kb + 8 * nj + 2 * t, k1 = k0 + 1;
                    if (k0 > r0) s[nj][0] = -1e30f;
                    if (k1 > r0) s[nj][1] = -1e30f;
                    if (k0 > r1) s[nj][2] = -1e30f;
                    if (k1 > r1) s[nj][3] = -1e30f;
                }
            }

            float mx0 = -1e30f, mx1 = -1e30f;
#pragma unroll
            for (int nj = 0; nj < 8; nj++) {
                mx0 = fmaxf(mx0, fmaxf(s[nj][0], s[nj][1]));
                mx1 = fmaxf(mx1, fmaxf(s[nj][2], s[nj][3]));
            }
            mx0 = fmaxf(mx0, __shfl_xor_sync(0xffffffffu, mx0, 1));
            mx0 = fmaxf(mx0, __shfl_xor_sync(0xffffffffu, mx0, 2));
            mx1 = fmaxf(mx1, __shfl_xor_sync(0xffffffffu, mx1, 1));
            mx1 = fmaxf(mx1, __shfl_xor_sync(0xffffffffu, mx1, 2));
            float mn0 = fmaxf(m0, mx0), mn1 = fmaxf(m1, mx1);
            float al0 = exp2f(m0 - mn0), al1 = exp2f(m1 - mn1);
            m0 = mn0; m1 = mn1;

            float rs0 = 0.f, rs1 = 0.f;
#pragma unroll
            for (int nj = 0; nj < 8; nj++) {
                s[nj][0] = exp2f(s[nj][0] - mn0);
                s[nj][1] = exp2f(s[nj][1] - mn0);
                s[nj][2] = exp2f(s[nj][2] - mn1);
                s[nj][3] = exp2f(s[nj][3] - mn1);
                rs0 += s[nj][0] + s[nj][1];
                rs1 += s[nj][2] + s[nj][3];
            }
            rs0 += __shfl_xor_sync(0xffffffffu, rs0, 1);
            rs0 += __shfl_xor_sync(0xffffffffu, rs0, 2);
            rs1 += __shfl_xor_sync(0xffffffffu, rs1, 1);
            rs1 += __shfl_xor_sync(0xffffffffu, rs1, 2);
            l0 = l0 * al0 + rs0;
            l1 = l1 * al1 + rs1;
#pragma unroll
            for (int nj = 0; nj < 8; nj++) {
                o[nj][0] *= al0; o[nj][1] *= al0;
                o[nj][2] *= al1; o[nj][3] *= al1;
            }

            uint32_t pf[4][4];
#pragma unroll
            for (int ksn = 0; ksn < 4; ksn++) {
                int ja = 2 * ksn, jb = ja + 1;
                pf[ksn][0] = packh(s[ja][0], s[ja][1]);
                pf[ksn][1] = packh(s[ja][2], s[ja][3]);
                pf[ksn][2] = packh(s[jb][0], s[jb][1]);
                pf[ksn][3] = packh(s[jb][2], s[jb][3]);
            }

#pragma unroll
            for (int nj = 0; nj < 8; nj++) {
                uint32_t co = tb + AT_V + (uint32_t)(nj * 16) + aoffV;
#pragma unroll
                for (int ksn = 0; ksn < 4; ksn++) {
                    uint32_t b0, b1;
                    LDSM_X2T(b0, b1, co + (uint32_t)(16 * ksn) * AT_STRIDE);
                    MMA_F16(o[nj], pf[ksn], b0, b1);
                }
            }
        }
    }

    // ---- epilogue: normalize, emit att fp16 in [b*s][h*hd] ----
    const float inv0 = 1.f / l0, inv1 = 1.f / l1;
    const int r0 = qbase + 16 * wid + g;
    const size_t base0 = ((size_t)bidx * S_LEN + r0) * DMODEL + hidx * 64 + 2 * t;
#pragma unroll
    for (int nj = 0; nj < 8; nj++) {
        float f0 = o[nj][0] * inv0, f1 = o[nj][1] * inv0;
        float f2 = o[nj][2] * inv1, f3 = o[nj][3] * inv1;
        size_t o0 = base0 + 8 * nj;
        size_t o1 = o0 + 8 * DMODEL;
        *(uint32_t*)(outh + o0) = packh(f0, f1);
        *(uint32_t*)(outh + o1) = packh(f2, f3);
    }
}

// ---------------- launch ----------------
extern "C" void kernel_launch(void* const* d_in, const int* in_sizes, int n_in,
                              void* d_out, int out_size)
{
    const float* x  = (const float*)d_in[0];
    const float* Wq = (const float*)d_in[1];
    const float* Wk = (const float*)d_in[2];
    const float* Wv = (const float*)d_in[3];
    const float* Wo = (const float*)d_in[4];
    float* out = (float*)d_out;

    __half *qh, *kh, *vh, *ah, *wth;
    cudaGetSymbolAddress((void**)&qh,  g_qh);
    cudaGetSymbolAddress((void**)&kh,  g_kh);
    cudaGetSymbolAddress((void**)&vh,  g_vh);
    cudaGetSymbolAddress((void**)&ah,  g_ah);
    cudaGetSymbolAddress((void**)&wth, g_wth);

    cudaFuncSetAttribute(gemm_mma_kernel, cudaFuncAttributeMaxDynamicSharedMemorySize, GEMM_SMEM);
    cudaFuncSetAttribute(attn_tc_kernel, cudaFuncAttributeMaxDynamicSharedMemorySize, ATT_SMEM);

    const int n4 = NTOK * DMODEL / 4;
    const size_t WSZ = (size_t)DMODEL * DMODEL;

    // x -> fp16; all 4 weights -> fp16 W^T in one launch
    convert_h_kernel<<<n4 / 256, 256>>>(x, ah, n4);
    convert_wt4_kernel<<<dim3(DMODEL / 32, DMODEL / 32, 4), dim3(32, 8)>>>(Wq, Wk, Wv, Wo, wth);

    // fused QKV projection (one launch, N = 3072) -> Q, K, V fp16 [b,h,s,hd]
    gemm_mma_kernel<<<dim3(3 * DMODEL / 128, NTOK / 128), 128, GEMM_SMEM>>>(
        ah, wth, nullptr, qh, kh, vh, 3);

    // fused causal attention -> att fp16
    attn_tc_kernel<<<dim3(S_LEN / 128, NBH), 256, ATT_SMEM>>>(qh, kh, vh, ah);

    // output projection
    gemm_mma_kernel<<<dim3(DMODEL / 128, NTOK / 128), 128, GEMM_SMEM>>>(
        ah, wth + 3 * WSZ, out, nullptr, nullptr, nullptr, 0);
}